// round 16
// baseline (speedup 1.0000x reference)
#include <cuda_runtime.h>
#include <cuda_fp16.h>
#include <math.h>
#include <stdint.h>

// ---------------------------------------------------------------------------
// Problem constants
// ---------------------------------------------------------------------------
#define BB       256
#define DIM      32768
#define SPLITS   64
#define CHUNK    (DIM / SPLITS)     // 512 fp16 cols per split
#define KB       32                 // k-block = 64 B/row
#define WPC      (CHUNK / KB)       // 16 k-blocks per CTA
#define STRIDE   80                 // smem row stride (64 B data + 16 B pad)
#define TILE_SM  (128 * STRIDE)     // 10240 B
#define STAGE    (2 * TILE_SM)      // 20480 B
#define NSTAGE   4
#define SMEM_TOTAL (NSTAGE * STAGE) // 81920 B -> 2 CTAs/SM (160 KB/SM)
#define MARGIN   0.003f
#define NSQP     2048               // convert blocks (1/8 row each)

// ---------------------------------------------------------------------------
// Static device scratch (no allocations anywhere)
// ---------------------------------------------------------------------------
__device__ __align__(16) __half g_h[BB * DIM];       // 16 MB fp16 copy of X
__device__ float  g_part[SPLITS * BB * BB];          // 16 MB split-K partials
__device__ float  g_sqp[NSQP];                       // per-block sum-of-squares
__device__ double g_lossp[BB];
__device__ double g_cntp[BB];
__device__ int    g_count;

// ---------------------------------------------------------------------------
// Helpers
// ---------------------------------------------------------------------------
__device__ __forceinline__ uint32_t smem_u32(const void* p) {
    uint32_t a;
    asm("{ .reg .u64 t; cvta.to.shared.u64 t, %1; cvt.u32.u64 %0, t; }" : "=r"(a) : "l"(p));
    return a;
}
__device__ __forceinline__ void cpasync16(uint32_t s, const void* g) {
    asm volatile("cp.async.cg.shared.global [%0], [%1], 16;" :: "r"(s), "l"(g) : "memory");
}
__device__ __forceinline__ void ldm_x4(uint32_t a, uint32_t& r0, uint32_t& r1,
                                       uint32_t& r2, uint32_t& r3) {
    asm volatile("ldmatrix.sync.aligned.m8n8.x4.shared.b16 {%0,%1,%2,%3}, [%4];"
                 : "=r"(r0), "=r"(r1), "=r"(r2), "=r"(r3) : "r"(a));
}
__device__ __forceinline__ void mma16816(float& c0, float& c1, float& c2, float& c3,
                                         uint32_t a0, uint32_t a1, uint32_t a2, uint32_t a3,
                                         uint32_t b0, uint32_t b1) {
    asm volatile(
        "mma.sync.aligned.m16n8k16.row.col.f32.f16.f16.f32 "
        "{%0,%1,%2,%3}, {%4,%5,%6,%7}, {%8,%9}, {%0,%1,%2,%3};"
        : "+f"(c0), "+f"(c1), "+f"(c2), "+f"(c3)
        : "r"(a0), "r"(a1), "r"(a2), "r"(a3), "r"(b0), "r"(b1));
}

// ---------------------------------------------------------------------------
// Kernel 1: fp32 -> fp16 convert, 16 elements/thread (4 independent float4
// loads -> MLP 4), + exact fp32 sum-of-squares partials (1 per block, 2048
// blocks, 8 per row). Resets g_count.
// ---------------------------------------------------------------------------
__global__ __launch_bounds__(256) void convert_kernel(const float* __restrict__ X) {
    const int b   = blockIdx.x;
    const int t   = threadIdx.x;
    const int gid = b * 256 + t;          // thread unit = 16 elements
    __shared__ float warr[8];

    const float4* s = reinterpret_cast<const float4*>(X) + (size_t)gid * 4;
    const float4 v0 = s[0];
    const float4 v1 = s[1];
    const float4 v2 = s[2];
    const float4 v3 = s[3];

    __half2 h[8];
    h[0] = __floats2half2_rn(v0.x, v0.y); h[1] = __floats2half2_rn(v0.z, v0.w);
    h[2] = __floats2half2_rn(v1.x, v1.y); h[3] = __floats2half2_rn(v1.z, v1.w);
    h[4] = __floats2half2_rn(v2.x, v2.y); h[5] = __floats2half2_rn(v2.z, v2.w);
    h[6] = __floats2half2_rn(v3.x, v3.y); h[7] = __floats2half2_rn(v3.z, v3.w);
    uint4 o0, o1;
    o0.x = *reinterpret_cast<uint32_t*>(&h[0]); o0.y = *reinterpret_cast<uint32_t*>(&h[1]);
    o0.z = *reinterpret_cast<uint32_t*>(&h[2]); o0.w = *reinterpret_cast<uint32_t*>(&h[3]);
    o1.x = *reinterpret_cast<uint32_t*>(&h[4]); o1.y = *reinterpret_cast<uint32_t*>(&h[5]);
    o1.z = *reinterpret_cast<uint32_t*>(&h[6]); o1.w = *reinterpret_cast<uint32_t*>(&h[7]);
    reinterpret_cast<uint4*>(g_h)[gid * 2 + 0] = o0;
    reinterpret_cast<uint4*>(g_h)[gid * 2 + 1] = o1;

    float sq = (v0.x*v0.x + v0.y*v0.y + v0.z*v0.z + v0.w*v0.w)
             + (v1.x*v1.x + v1.y*v1.y + v1.z*v1.z + v1.w*v1.w)
             + (v2.x*v2.x + v2.y*v2.y + v2.z*v2.z + v2.w*v2.w)
             + (v3.x*v3.x + v3.y*v3.y + v3.z*v3.z + v3.w*v3.w);
#pragma unroll
    for (int o = 16; o > 0; o >>= 1) sq += __shfl_xor_sync(0xFFFFFFFFu, sq, o);
    if ((t & 31) == 0) warr[t >> 5] = sq;
    __syncthreads();
    if (t == 0) {
        float ssum = 0.f;
#pragma unroll
        for (int i = 0; i < 8; i++) ssum += warr[i];
        g_sqp[b] = ssum;
    }
    if (b == 0 && t == 0) g_count = 0;
}

// ---------------------------------------------------------------------------
// Kernel 2: split-K fp16 GEMM, 2 CTAs/SM, 4-stage cp.async ring.
//   grid (SPLITS, 4): blockIdx.y -> (mt, nt) 2x2 tiles of 128x128.
//   Race-free: prefetch of stage (ii+3)%4 == (ii-1)%4 is issued only after
//   the barrier that retires iteration ii-1's readers.
// ---------------------------------------------------------------------------
extern __shared__ unsigned char dsm[];

__global__ __launch_bounds__(256, 2) void gemm_kernel() {
    const int split = blockIdx.x;
    const int mt = blockIdx.y & 1;
    const int nt = blockIdx.y >> 1;
    const int t    = threadIdx.x;
    const int w    = t >> 5;
    const int lane = t & 31;
    const int wm   = w >> 2;
    const int wn   = w & 3;

    const uint32_t sb = smem_u32(dsm);
    const int chunk0 = split * CHUNK;

    const __half* gA = g_h + (size_t)(mt * 128) * DIM + chunk0;
    const __half* gB = g_h + (size_t)(nt * 128) * DIM + chunk0;

    float acc[4][4][4];
#pragma unroll
    for (int i = 0; i < 4; i++)
#pragma unroll
        for (int j = 0; j < 4; j++)
#pragma unroll
            for (int r = 0; r < 4; r++) acc[i][j][r] = 0.f;

    // per k-block: 2 tiles x 128 rows x 4 x 16B segs = 1024 segs, 4 per thread
    auto issue = [&](int kb, int st_idx) {
        const uint32_t st = sb + st_idx * STAGE;
        const int kcol = kb * KB;
#pragma unroll
        for (int i = 0; i < 4; i++) {
            const int idx = t + 256 * i;
            const int ab  = idx >> 9;        // 0 = A, 1 = B
            const int s2  = idx & 511;
            const int row = s2 >> 2;
            const int c   = s2 & 3;
            const __half* gp = (ab ? gB : gA) + (size_t)row * DIM + kcol + c * 8;
            cpasync16(st + ab * TILE_SM + row * STRIDE + c * 16, gp);
        }
        asm volatile("cp.async.commit_group;" ::: "memory");
    };

    issue(0, 0);
    issue(1, 1);
    issue(2, 2);

    const uint32_t a_ld = (uint32_t)(wm * 64 + (lane & 15)) * STRIDE + ((lane >> 4) & 1) * 16;
    const int bsel  = (lane >> 3) & 3;
    const uint32_t b_ld = (uint32_t)(wn * 32 + ((bsel >> 1) * 8) + (lane & 7)) * STRIDE
                        + (bsel & 1) * 16;

    for (int ii = 0; ii < WPC; ii++) {
        const int st_idx = ii % NSTAGE;
        // retire the group for stage st_idx (up to 3 groups in flight)
        if (ii + 2 < WPC) {
            asm volatile("cp.async.wait_group 2;" ::: "memory");
        } else if (ii + 1 < WPC) {
            asm volatile("cp.async.wait_group 1;" ::: "memory");
        } else {
            asm volatile("cp.async.wait_group 0;" ::: "memory");
        }
        __syncthreads();   // readers of stage (ii-1) retired; stage st_idx ready
        if (ii + 3 < WPC) issue(ii + 3, (ii + 3) % NSTAGE);

        const uint32_t st = sb + st_idx * STAGE;
#pragma unroll
        for (int ks = 0; ks < 2; ks++) {
            const uint32_t ko = ks * 32;
            uint32_t af[4][4];
#pragma unroll
            for (int i = 0; i < 4; i++)
                ldm_x4(st + a_ld + (uint32_t)i * 16 * STRIDE + ko,
                       af[i][0], af[i][1], af[i][2], af[i][3]);
            uint32_t bf[2][4];
#pragma unroll
            for (int p = 0; p < 2; p++)
                ldm_x4(st + TILE_SM + b_ld + (uint32_t)p * 16 * STRIDE + ko,
                       bf[p][0], bf[p][1], bf[p][2], bf[p][3]);
#pragma unroll
            for (int i = 0; i < 4; i++)
#pragma unroll
                for (int j = 0; j < 4; j++) {
                    const int p = j >> 1, h = (j & 1) * 2;
                    mma16816(acc[i][j][0], acc[i][j][1], acc[i][j][2], acc[i][j][3],
                             af[i][0], af[i][1], af[i][2], af[i][3],
                             bf[p][h], bf[p][h + 1]);
                }
        }
    }

    float* out = g_part + ((size_t)split << 16);
    const int rbase = mt * 128 + wm * 64 + (lane >> 2);
    const int cbase = nt * 128 + wn * 32 + (lane & 3) * 2;
#pragma unroll
    for (int i = 0; i < 4; i++)
#pragma unroll
        for (int j = 0; j < 4; j++) {
            const int r0 = rbase + i * 16;
            const int c  = cbase + j * 8;
            *reinterpret_cast<float2*>(out + r0 * BB + c)       = make_float2(acc[i][j][0], acc[i][j][1]);
            *reinterpret_cast<float2*>(out + (r0 + 8) * BB + c) = make_float2(acc[i][j][2], acc[i][j][3]);
        }
}

// ---------------------------------------------------------------------------
// Kernel 3: loss, block-per-anchor, G-row reduced on the fly from the 64
// split partials (coalesced, 8-way batched for MLP). Exact fp32 norms from
// g_sqp (8 partials per row). Impostor-major inner loop, fused final.
// ---------------------------------------------------------------------------
__global__ __launch_bounds__(256) void loss_kernel(const int* __restrict__ mods,
                                                   float* __restrict__ out) {
    const int a = blockIdx.x;
    const int t = threadIdx.x;
    const int w = t >> 5;
    const int lane = t & 31;
    __shared__ int    smod[BB];
    __shared__ float  sqs[BB];
    __shared__ float  pv[BB + 8];
    __shared__ int    wpos[8], wimp[8];
    __shared__ double dacc[BB];
    __shared__ int    is_last;

    smod[t] = mods[t];
    {
        const float* qp = g_sqp + t * 8;   // 8 partials per row
        float ssum = 0.f;
#pragma unroll
        for (int i = 0; i < 8; i++) ssum += qp[i];
        sqs[t] = ssum;
    }
    __syncthreads();

    // reduce G[a, t] over 64 splits (stride 64K floats; coalesced across t)
    float gv;
    {
        const float* rp = g_part + a * BB + t;
        float s0 = 0.f, s1 = 0.f, s2 = 0.f, s3 = 0.f;
        float s4 = 0.f, s5 = 0.f, s6 = 0.f, s7 = 0.f;
#pragma unroll
        for (int p = 0; p < SPLITS; p += 8) {
            s0 += rp[(size_t)(p + 0) << 16];
            s1 += rp[(size_t)(p + 1) << 16];
            s2 += rp[(size_t)(p + 2) << 16];
            s3 += rp[(size_t)(p + 3) << 16];
            s4 += rp[(size_t)(p + 4) << 16];
            s5 += rp[(size_t)(p + 5) << 16];
            s6 += rp[(size_t)(p + 6) << 16];
            s7 += rp[(size_t)(p + 7) << 16];
        }
        gv = ((s0 + s1) + (s2 + s3)) + ((s4 + s5) + (s6 + s7));
    }

    const int ma = smod[a];
    float d2 = fmaxf(sqs[a] + sqs[t] - 2.f * gv, 0.f);
    const float dv = (d2 > 0.f) ? sqrtf(d2) : 0.f;

    const bool imp = (smod[t] != ma);
    const bool pos = (t != a) && !imp;

    const uint32_t bp = __ballot_sync(0xFFFFFFFFu, pos);
    const uint32_t bi = __ballot_sync(0xFFFFFFFFu, imp);
    if (lane == 0) { wpos[w] = __popc(bp); wimp[w] = __popc(bi); }
    __syncthreads();

    int base = 0, nPos = 0, nImp = 0;
#pragma unroll
    for (int i = 0; i < 8; i++) {
        if (i < w) base += wpos[i];
        nPos += wpos[i];
        nImp += wimp[i];
    }
    if (pos) pv[base + __popc(bp & ((1u << lane) - 1u))] = dv + MARGIN;
    if (t < 8) pv[nPos + t] = -1e30f;   // padding: relu self-masks
    __syncthreads();

    float a0 = 0.f, a1 = 0.f;
    if (imp) {
        const float dak = dv;
        const int n8 = (nPos + 7) & ~7;
#pragma unroll 1
        for (int i = 0; i < n8; i += 8) {
            a0 += fmaxf(pv[i + 0] - dak, 0.f);
            a1 += fmaxf(pv[i + 1] - dak, 0.f);
            a0 += fmaxf(pv[i + 2] - dak, 0.f);
            a1 += fmaxf(pv[i + 3] - dak, 0.f);
            a0 += fmaxf(pv[i + 4] - dak, 0.f);
            a1 += fmaxf(pv[i + 5] - dak, 0.f);
            a0 += fmaxf(pv[i + 6] - dak, 0.f);
            a1 += fmaxf(pv[i + 7] - dak, 0.f);
        }
    }
    dacc[t] = (double)(a0 + a1);
    __syncthreads();
    for (int stride = 128; stride > 0; stride >>= 1) {
        if (t < stride) dacc[t] += dacc[t + stride];
        __syncthreads();
    }
    if (t == 0) {
        g_lossp[a] = dacc[0];
        g_cntp[a]  = (double)nPos * (double)nImp;
    }

    __threadfence();
    if (t == 0) {
        int old = atomicAdd(&g_count, 1);
        is_last = (old == BB - 1);
    }
    __syncthreads();
    if (is_last) {
        __threadfence();
        __shared__ double scnt2[BB];
        dacc[t]  = g_lossp[t];
        scnt2[t] = g_cntp[t];
        __syncthreads();
        for (int stride = 128; stride > 0; stride >>= 1) {
            if (t < stride) { dacc[t] += dacc[t + stride]; scnt2[t] += scnt2[t + stride]; }
            __syncthreads();
        }
        if (t == 0) out[0] = (float)(dacc[0] / scnt2[0]);
    }
}

// ---------------------------------------------------------------------------
extern "C" void kernel_launch(void* const* d_in, const int* in_sizes, int n_in,
                              void* d_out, int out_size) {
    const float* X    = (const float*)d_in[0];
    const int*   mods = (const int*)  d_in[1];
    (void)in_sizes; (void)n_in; (void)out_size;

    cudaFuncSetAttribute(gemm_kernel, cudaFuncAttributeMaxDynamicSharedMemorySize, SMEM_TOTAL);

    convert_kernel<<<NSQP, 256>>>(X);
    gemm_kernel<<<dim3(SPLITS, 4), 256, SMEM_TOTAL>>>();
    loss_kernel<<<BB, 256>>>(mods, (float*)d_out);
}

// round 17
// speedup vs baseline: 1.1633x; 1.1633x over previous
#include <cuda_runtime.h>
#include <cuda_fp16.h>
#include <math.h>
#include <stdint.h>

// ---------------------------------------------------------------------------
// Problem constants
// ---------------------------------------------------------------------------
#define BB       256
#define DIM      32768
#define SPLITS   64
#define CHUNK    (DIM / SPLITS)     // 512 fp16 cols per split
#define KB       32                 // k-block = 64 B/row
#define WPC      (CHUNK / KB)       // 16 k-blocks per CTA
#define STRIDE   80                 // smem row stride (64 B data + 16 B pad)
#define TILE_SM  (128 * STRIDE)     // 10240 B
#define STAGE    (2 * TILE_SM)      // 20480 B
#define NSTAGE   3
#define SMEM_TOTAL (NSTAGE * STAGE) // 61440 B -> 2 CTAs/SM
#define MARGIN   0.003f
#define NSQP     2048               // convert blocks (1/8 row each)

// ---------------------------------------------------------------------------
// Static device scratch (no allocations anywhere)
// ---------------------------------------------------------------------------
__device__ __align__(16) __half g_h[BB * DIM];       // 16 MB fp16 copy of X
__device__ float  g_part[SPLITS * BB * BB];          // 16 MB split-K partials
__device__ float  g_sqp[NSQP];                       // per-block sum-of-squares
__device__ double g_lossp[BB];
__device__ double g_cntp[BB];
__device__ int    g_count;

// ---------------------------------------------------------------------------
// Helpers
// ---------------------------------------------------------------------------
__device__ __forceinline__ uint32_t smem_u32(const void* p) {
    uint32_t a;
    asm("{ .reg .u64 t; cvta.to.shared.u64 t, %1; cvt.u32.u64 %0, t; }" : "=r"(a) : "l"(p));
    return a;
}
__device__ __forceinline__ void cpasync16(uint32_t s, const void* g) {
    asm volatile("cp.async.cg.shared.global [%0], [%1], 16;" :: "r"(s), "l"(g) : "memory");
}
__device__ __forceinline__ void ldm_x4(uint32_t a, uint32_t& r0, uint32_t& r1,
                                       uint32_t& r2, uint32_t& r3) {
    asm volatile("ldmatrix.sync.aligned.m8n8.x4.shared.b16 {%0,%1,%2,%3}, [%4];"
                 : "=r"(r0), "=r"(r1), "=r"(r2), "=r"(r3) : "r"(a));
}
__device__ __forceinline__ void mma16816(float& c0, float& c1, float& c2, float& c3,
                                         uint32_t a0, uint32_t a1, uint32_t a2, uint32_t a3,
                                         uint32_t b0, uint32_t b1) {
    asm volatile(
        "mma.sync.aligned.m16n8k16.row.col.f32.f16.f16.f32 "
        "{%0,%1,%2,%3}, {%4,%5,%6,%7}, {%8,%9}, {%0,%1,%2,%3};"
        : "+f"(c0), "+f"(c1), "+f"(c2), "+f"(c3)
        : "r"(a0), "r"(a1), "r"(a2), "r"(a3), "r"(b0), "r"(b1));
}

// ---------------------------------------------------------------------------
// Kernel 1: fp32 -> fp16 convert, FULLY COALESCED.
// Thread t, iter it handles float4 index b*1024 + it*256 + t:
//   loads  -> 16B at 16B lane stride (perfect 512B/warp wavefronts)
//   stores -> uint2 (8B = 8 fp16) at 8B lane stride (perfect 256B/warp)
// 4 independent loads issued up front (MLP 4). Block b covers 4096 floats =
// 1/8 of a row; exact fp32 sum-of-squares partial to g_sqp[b]. Resets g_count.
// ---------------------------------------------------------------------------
__global__ __launch_bounds__(256) void convert_kernel(const float* __restrict__ X) {
    const int b = blockIdx.x;
    const int t = threadIdx.x;
    __shared__ float warr[8];

    const float4* Xf4 = reinterpret_cast<const float4*>(X);
    uint2*        Hq2 = reinterpret_cast<uint2*>(g_h);
    const int base = b * 1024 + t;

    float4 v[4];
#pragma unroll
    for (int it = 0; it < 4; it++) v[it] = Xf4[base + it * 256];

    float sq = 0.f;
#pragma unroll
    for (int it = 0; it < 4; it++) {
        __half2 lo = __floats2half2_rn(v[it].x, v[it].y);
        __half2 hi = __floats2half2_rn(v[it].z, v[it].w);
        uint2 o;
        o.x = *reinterpret_cast<uint32_t*>(&lo);
        o.y = *reinterpret_cast<uint32_t*>(&hi);
        Hq2[base + it * 256] = o;
        sq += v[it].x * v[it].x + v[it].y * v[it].y
            + v[it].z * v[it].z + v[it].w * v[it].w;
    }

#pragma unroll
    for (int o = 16; o > 0; o >>= 1) sq += __shfl_xor_sync(0xFFFFFFFFu, sq, o);
    if ((t & 31) == 0) warr[t >> 5] = sq;
    __syncthreads();
    if (t == 0) {
        float ssum = 0.f;
#pragma unroll
        for (int i = 0; i < 8; i++) ssum += warr[i];
        g_sqp[b] = ssum;
    }
    if (b == 0 && t == 0) g_count = 0;
}

// ---------------------------------------------------------------------------
// Kernel 2: split-K fp16 GEMM, 2 CTAs/SM (60 KB smem), 3-stage cp.async ring.
//   grid (SPLITS, 4): blockIdx.y -> (mt, nt) 2x2 tiles of 128x128.
//   Race-free: prefetch issued only after the barrier retiring prior readers.
//   (Measured-best GEMM form from R14.)
// ---------------------------------------------------------------------------
extern __shared__ unsigned char dsm[];

__global__ __launch_bounds__(256, 2) void gemm_kernel() {
    const int split = blockIdx.x;
    const int mt = blockIdx.y & 1;
    const int nt = blockIdx.y >> 1;
    const int t    = threadIdx.x;
    const int w    = t >> 5;
    const int lane = t & 31;
    const int wm   = w >> 2;
    const int wn   = w & 3;

    const uint32_t sb = smem_u32(dsm);
    const int chunk0 = split * CHUNK;

    const __half* gA = g_h + (size_t)(mt * 128) * DIM + chunk0;
    const __half* gB = g_h + (size_t)(nt * 128) * DIM + chunk0;

    float acc[4][4][4];
#pragma unroll
    for (int i = 0; i < 4; i++)
#pragma unroll
        for (int j = 0; j < 4; j++)
#pragma unroll
            for (int r = 0; r < 4; r++) acc[i][j][r] = 0.f;

    // per k-block: 2 tiles x 128 rows x 4 x 16B segs = 1024 segs, 4 per thread
    auto issue = [&](int kb, int st_idx) {
        const uint32_t st = sb + st_idx * STAGE;
        const int kcol = kb * KB;
#pragma unroll
        for (int i = 0; i < 4; i++) {
            const int idx = t + 256 * i;
            const int ab  = idx >> 9;        // 0 = A, 1 = B
            const int s2  = idx & 511;
            const int row = s2 >> 2;
            const int c   = s2 & 3;
            const __half* gp = (ab ? gB : gA) + (size_t)row * DIM + kcol + c * 8;
            cpasync16(st + ab * TILE_SM + row * STRIDE + c * 16, gp);
        }
        asm volatile("cp.async.commit_group;" ::: "memory");
    };

    issue(0, 0);
    issue(1, 1);

    const uint32_t a_ld = (uint32_t)(wm * 64 + (lane & 15)) * STRIDE + ((lane >> 4) & 1) * 16;
    const int bsel  = (lane >> 3) & 3;
    const uint32_t b_ld = (uint32_t)(wn * 32 + ((bsel >> 1) * 8) + (lane & 7)) * STRIDE
                        + (bsel & 1) * 16;

    for (int ii = 0; ii < WPC; ii++) {
        const int st_idx = ii % NSTAGE;
        if (ii + 1 < WPC) {
            asm volatile("cp.async.wait_group 1;" ::: "memory");
        } else {
            asm volatile("cp.async.wait_group 0;" ::: "memory");
        }
        __syncthreads();   // readers of stage (ii-1) retired; stage st_idx ready
        if (ii + 2 < WPC) issue(ii + 2, (ii + 2) % NSTAGE);

        const uint32_t st = sb + st_idx * STAGE;
#pragma unroll
        for (int ks = 0; ks < 2; ks++) {
            const uint32_t ko = ks * 32;
            uint32_t af[4][4];
#pragma unroll
            for (int i = 0; i < 4; i++)
                ldm_x4(st + a_ld + (uint32_t)i * 16 * STRIDE + ko,
                       af[i][0], af[i][1], af[i][2], af[i][3]);
            uint32_t bf[2][4];
#pragma unroll
            for (int p = 0; p < 2; p++)
                ldm_x4(st + TILE_SM + b_ld + (uint32_t)p * 16 * STRIDE + ko,
                       bf[p][0], bf[p][1], bf[p][2], bf[p][3]);
#pragma unroll
            for (int i = 0; i < 4; i++)
#pragma unroll
                for (int j = 0; j < 4; j++) {
                    const int p = j >> 1, h = (j & 1) * 2;
                    mma16816(acc[i][j][0], acc[i][j][1], acc[i][j][2], acc[i][j][3],
                             af[i][0], af[i][1], af[i][2], af[i][3],
                             bf[p][h], bf[p][h + 1]);
                }
        }
    }

    float* out = g_part + ((size_t)split << 16);
    const int rbase = mt * 128 + wm * 64 + (lane >> 2);
    const int cbase = nt * 128 + wn * 32 + (lane & 3) * 2;
#pragma unroll
    for (int i = 0; i < 4; i++)
#pragma unroll
        for (int j = 0; j < 4; j++) {
            const int r0 = rbase + i * 16;
            const int c  = cbase + j * 8;
            *reinterpret_cast<float2*>(out + r0 * BB + c)       = make_float2(acc[i][j][0], acc[i][j][1]);
            *reinterpret_cast<float2*>(out + (r0 + 8) * BB + c) = make_float2(acc[i][j][2], acc[i][j][3]);
        }
}

// ---------------------------------------------------------------------------
// Kernel 3: loss, block-per-anchor, G-row reduced on the fly from the 64
// split partials (coalesced, 8-way batched for MLP). Exact fp32 norms from
// g_sqp (8 partials per row). Impostor-major inner loop, fused final.
// ---------------------------------------------------------------------------
__global__ __launch_bounds__(256) void loss_kernel(const int* __restrict__ mods,
                                                   float* __restrict__ out) {
    const int a = blockIdx.x;
    const int t = threadIdx.x;
    const int w = t >> 5;
    const int lane = t & 31;
    __shared__ int    smod[BB];
    __shared__ float  sqs[BB];
    __shared__ float  pv[BB + 8];
    __shared__ int    wpos[8], wimp[8];
    __shared__ double dacc[BB];
    __shared__ int    is_last;

    smod[t] = mods[t];
    {
        const float* qp = g_sqp + t * 8;   // 8 partials per row
        float ssum = 0.f;
#pragma unroll
        for (int i = 0; i < 8; i++) ssum += qp[i];
        sqs[t] = ssum;
    }
    __syncthreads();

    // reduce G[a, t] over 64 splits (stride 64K floats; coalesced across t)
    float gv;
    {
        const float* rp = g_part + a * BB + t;
        float s0 = 0.f, s1 = 0.f, s2 = 0.f, s3 = 0.f;
        float s4 = 0.f, s5 = 0.f, s6 = 0.f, s7 = 0.f;
#pragma unroll
        for (int p = 0; p < SPLITS; p += 8) {
            s0 += rp[(size_t)(p + 0) << 16];
            s1 += rp[(size_t)(p + 1) << 16];
            s2 += rp[(size_t)(p + 2) << 16];
            s3 += rp[(size_t)(p + 3) << 16];
            s4 += rp[(size_t)(p + 4) << 16];
            s5 += rp[(size_t)(p + 5) << 16];
            s6 += rp[(size_t)(p + 6) << 16];
            s7 += rp[(size_t)(p + 7) << 16];
        }
        gv = ((s0 + s1) + (s2 + s3)) + ((s4 + s5) + (s6 + s7));
    }

    const int ma = smod[a];
    float d2 = fmaxf(sqs[a] + sqs[t] - 2.f * gv, 0.f);
    const float dv = (d2 > 0.f) ? sqrtf(d2) : 0.f;

    const bool imp = (smod[t] != ma);
    const bool pos = (t != a) && !imp;

    const uint32_t bp = __ballot_sync(0xFFFFFFFFu, pos);
    const uint32_t bi = __ballot_sync(0xFFFFFFFFu, imp);
    if (lane == 0) { wpos[w] = __popc(bp); wimp[w] = __popc(bi); }
    __syncthreads();

    int base = 0, nPos = 0, nImp = 0;
#pragma unroll
    for (int i = 0; i < 8; i++) {
        if (i < w) base += wpos[i];
        nPos += wpos[i];
        nImp += wimp[i];
    }
    if (pos) pv[base + __popc(bp & ((1u << lane) - 1u))] = dv + MARGIN;
    if (t < 8) pv[nPos + t] = -1e30f;   // padding: relu self-masks
    __syncthreads();

    float a0 = 0.f, a1 = 0.f;
    if (imp) {
        const float dak = dv;
        const int n8 = (nPos + 7) & ~7;
#pragma unroll 1
        for (int i = 0; i < n8; i += 8) {
            a0 += fmaxf(pv[i + 0] - dak, 0.f);
            a1 += fmaxf(pv[i + 1] - dak, 0.f);
            a0 += fmaxf(pv[i + 2] - dak, 0.f);
            a1 += fmaxf(pv[i + 3] - dak, 0.f);
            a0 += fmaxf(pv[i + 4] - dak, 0.f);
            a1 += fmaxf(pv[i + 5] - dak, 0.f);
            a0 += fmaxf(pv[i + 6] - dak, 0.f);
            a1 += fmaxf(pv[i + 7] - dak, 0.f);
        }
    }
    dacc[t] = (double)(a0 + a1);
    __syncthreads();
    for (int stride = 128; stride > 0; stride >>= 1) {
        if (t < stride) dacc[t] += dacc[t + stride];
        __syncthreads();
    }
    if (t == 0) {
        g_lossp[a] = dacc[0];
        g_cntp[a]  = (double)nPos * (double)nImp;
    }

    __threadfence();
    if (t == 0) {
        int old = atomicAdd(&g_count, 1);
        is_last = (old == BB - 1);
    }
    __syncthreads();
    if (is_last) {
        __threadfence();
        __shared__ double scnt2[BB];
        dacc[t]  = g_lossp[t];
        scnt2[t] = g_cntp[t];
        __syncthreads();
        for (int stride = 128; stride > 0; stride >>= 1) {
            if (t < stride) { dacc[t] += dacc[t + stride]; scnt2[t] += scnt2[t + stride]; }
            __syncthreads();
        }
        if (t == 0) out[0] = (float)(dacc[0] / scnt2[0]);
    }
}

// ---------------------------------------------------------------------------
extern "C" void kernel_launch(void* const* d_in, const int* in_sizes, int n_in,
                              void* d_out, int out_size) {
    const float* X    = (const float*)d_in[0];
    const int*   mods = (const int*)  d_in[1];
    (void)in_sizes; (void)n_in; (void)out_size;

    cudaFuncSetAttribute(gemm_kernel, cudaFuncAttributeMaxDynamicSharedMemorySize, SMEM_TOTAL);

    convert_kernel<<<NSQP, 256>>>(X);
    gemm_kernel<<<dim3(SPLITS, 4), 256, SMEM_TOTAL>>>();
    loss_kernel<<<BB, 256>>>(mods, (float*)d_out);
}